// round 11
// baseline (speedup 1.0000x reference)
#include <cuda_runtime.h>

#define NQ    14
#define NS    16384
#define NTH   512
#define BATCH 512
#define GRID  152
#define PAD_SLOTS 16960   // max P(j) = 16383+511+60 = 16954

typedef unsigned long long u64;

// ---------------- INVERSE MCX permutation table + work counter --------------
__device__ unsigned short d_permtab[NS];
__device__ int d_ctr;

__global__ void build_perm_kernel() {
    int i = blockIdx.x * blockDim.x + threadIdx.x;
    if (i == 0) d_ctr = 0;
    unsigned x = (unsigned)i;
#pragma unroll
    for (int w = NQ - 1; w >= 0; w--) {
        const int p1 = NQ - 1 - w;
        const int p2 = NQ - 1 - ((w + 1) % NQ);
        const int pt = NQ - 1 - ((w + 2) % NQ);
        unsigned b1 = (x >> p1) & 1u;
        unsigned b2 = (x >> p2) & 1u;
        x ^= ((b1 & (b2 ^ 1u)) << pt);
    }
    d_permtab[i] = (unsigned short)x;
}

// ---------------- packed f32x2 primitives ------------------------------------
__device__ __forceinline__ u64 mul2(u64 a, u64 b) {
    u64 d; asm("mul.rn.f32x2 %0,%1,%2;" : "=l"(d) : "l"(a), "l"(b)); return d;
}
__device__ __forceinline__ u64 fma2(u64 a, u64 b, u64 c) {
    u64 d; asm("fma.rn.f32x2 %0,%1,%2,%3;" : "=l"(d) : "l"(a), "l"(b), "l"(c)); return d;
}
__device__ __forceinline__ u64 pk2(float lo, float hi) {
    u64 d; asm("mov.b64 %0,{%1,%2};" : "=l"(d) : "f"(lo), "f"(hi)); return d;
}
__device__ __forceinline__ void up2(u64 v, float& lo, float& hi) {
    asm("mov.b64 {%0,%1},%2;" : "=f"(lo), "=f"(hi) : "l"(v));
}
__device__ __forceinline__ u64 swp(u64 v) {
    float lo, hi; up2(v, lo, hi); return pk2(hi, lo);
}
__device__ __forceinline__ u64 shx(u64 v, int m) {
    return __shfl_xor_sync(0xffffffffu, v, m);
}

struct Gf { u64 T, Tn; };
__device__ __forceinline__ Gf mkgf(float t) {
    Gf g; g.T = pk2(t, t); g.Tn = pk2(-t, -t); return g;
}

// scaled mix: x' = x - i t y ; y' = y - i t x
__device__ __forceinline__ void mix2f(u64& Xr, u64& Xi, u64& Yr, u64& Yi, const Gf& g) {
    u64 xr = Xr, xi = Xi, yr = Yr, yi = Yi;
    Xr = fma2(g.T,  yi, xr);
    Xi = fma2(g.Tn, yr, xi);
    Yr = fma2(g.T,  xi, yr);
    Yi = fma2(g.Tn, xr, yi);
}

template <int MA, int MB>
__device__ __forceinline__ void xxf(u64* Ar, u64* Ai, const Gf& g) {
    const int M = MA | MB;
#pragma unroll
    for (int t = 0; t < 16; t++) {
        if (t & M) continue;
        mix2f(Ar[t],      Ai[t],      Ar[t ^ M],  Ai[t ^ M],  g);
        mix2f(Ar[t | MA], Ai[t | MA], Ar[t | MB], Ai[t | MB], g);
    }
}
template <int M>
__device__ __forceinline__ void rxf(u64* Ar, u64* Ai, const Gf& g) {
#pragma unroll
    for (int t = 0; t < 16; t++) {
        if (t & M) continue;
        mix2f(Ar[t], Ai[t], Ar[t | M], Ai[t | M], g);
    }
}
template <int M>
__device__ __forceinline__ void rzf(u64* Ar, u64* Ai, const Gf& g) {
#pragma unroll
    for (int t = 0; t < 16; t++) {
        u64 r = Ar[t], i = Ai[t];
        if (t & M) {
            Ar[t] = fma2(g.Tn, i, r);
            Ai[t] = fma2(g.T,  r, i);
        } else {
            Ar[t] = fma2(g.T,  i, r);
            Ai[t] = fma2(g.Tn, r, i);
        }
    }
}
// lane shuffle gate (XX or Rx on lane bits with xor-mask m): v' = v - i t v_p
__device__ __forceinline__ void lgate(u64* Ar, u64* Ai, float t, int m) {
    u64 T = pk2(t, t), Tn = pk2(-t, -t);
#pragma unroll
    for (int q = 0; q < 16; q++) {
        u64 pr = shx(Ar[q], m), pi = shx(Ai[q], m);
        Ar[q] = fma2(T,  pi, Ar[q]);
        Ai[q] = fma2(Tn, pr, Ai[q]);
    }
}
__device__ __forceinline__ void scale32(u64* Ar, u64* Ai, float k) {
    u64 K = pk2(k, k);
#pragma unroll
    for (int t = 0; t < 16; t++) { Ar[t] = mul2(K, Ar[t]); Ai[t] = mul2(K, Ai[t]); }
}

// (-i)^k rotation
__device__ __forceinline__ void rot_mi(int k, float r, float i, float& orr, float& oi) {
    switch (k & 3) {
        case 0:  orr = r;  oi = i;  break;
        case 1:  orr = i;  oi = -r; break;
        case 2:  orr = -r; oi = -i; break;
        default: orr = -i; oi = r;  break;
    }
}

// one component of  Rz(wa)Rz(wb) * XX(phi) * (Rx|0> (x) Rx|0>)  on a wire pair
__device__ void pair_component(const float* p, const float* cp, int b,
                               int wa, int wb, int xxidx, int sel,
                               float& outr, float& outi) {
    float ca, sa, cbw, sbw, cx, sx;
    sincosf(0.5f * p[b * 42 + wa], &sa, &ca);
    sincosf(0.5f * p[b * 42 + wb], &sbw, &cbw);
    sincosf(0.5f * cp[b * 14 + xxidx], &sx, &cx);
    float vr[4] = {ca * cbw, 0.0f, 0.0f, -sa * sbw};
    float vi[4] = {0.0f, -ca * sbw, -sa * cbw, 0.0f};
    float nr[4], ni[4];
    nr[0] = cx * vr[0] + sx * vi[3]; ni[0] = cx * vi[0] - sx * vr[3];
    nr[3] = cx * vr[3] + sx * vi[0]; ni[3] = cx * vi[3] - sx * vr[0];
    nr[1] = cx * vr[1] + sx * vi[2]; ni[1] = cx * vi[1] - sx * vr[2];
    nr[2] = cx * vr[2] + sx * vi[1]; ni[2] = cx * vi[2] - sx * vr[1];
    float tha = p[b * 42 + 14 + wa], thb = p[b * 42 + 14 + wb];
    float ph = 0.5f * (((sel >> 1) ? tha : -tha) + ((sel & 1) ? thb : -thb));
    float cph, sph; sincosf(ph, &sph, &cph);
    float ur = nr[sel], ui = ni[sel];
    outr = ur * cph - ui * sph;
    outi = ui * cph + ur * sph;
}

// ---------------- main kernel ------------------------------------------------
__global__ void __launch_bounds__(NTH, 1)
quantum_kernel(const float* __restrict__ cp, const float* __restrict__ p,
               float* __restrict__ out) {
    extern __shared__ float sm[];
    float* RE = sm;
    float* IM = sm + PAD_SLOTS;

    __shared__ float c1[NQ], s1[NQ];
    __shared__ float txv[NQ];          // tan(xx half): [0..6]=a, [7..13]=b
    __shared__ float t3[NQ];           // tan(rx3 half)
    __shared__ float tz[NQ];           // tan(rz half)
    __shared__ float cxc[NQ], c3c[NQ], czc[NQ];
    __shared__ float Whr[16], Whi[16];   // wires 0-3 table (prefix + XXb(1,2), Rx3(1,2))
    __shared__ float chi_r[4], chi_i[4]; // wires 12,13 prefix table
    __shared__ float kapA[3];
    __shared__ float red[16][11];
    __shared__ int sm_b;

    const int tid = threadIdx.x;

    for (;;) {
        if (tid == 0) sm_b = atomicAdd(&d_ctr, 1);
        __syncthreads();
        const int b = sm_b;
        if (b >= BATCH) break;

        // ---------------- setup (single stage) ----------------
        if (tid < 32) {
            float fvr = 0.0f, fvi = 0.0f;
            if (tid < 16) {
                float w1r, w1i, w2r, w2i;
                pair_component(p, cp, b, 0, 1, 0, tid >> 2, w1r, w1i);
                pair_component(p, cp, b, 2, 3, 1, tid & 3,  w2r, w2i);
                fvr = w1r * w2r - w1i * w2i;
                fvi = w1r * w2i + w1i * w2r;
            } else if (tid < 20) {
                float cr_, ci_;
                pair_component(p, cp, b, 12, 13, 6, tid - 16, cr_, ci_);
                chi_r[tid - 16] = cr_; chi_i[tid - 16] = ci_;
            }
            __syncwarp();
            // fold XXb(1,2), Rx3(1), Rx3(2) into W via warp shuffles (exact)
            float cx, sx, pr_, pi_, nr_, ni_;
            sincosf(0.5f * cp[b * NQ + 7], &sx, &cx);        // XXb(1,2): mask 6
            pr_ = __shfl_xor_sync(0xffffffffu, fvr, 6);
            pi_ = __shfl_xor_sync(0xffffffffu, fvi, 6);
            nr_ = cx * fvr + sx * pi_; ni_ = cx * fvi - sx * pr_;
            fvr = nr_; fvi = ni_;
            sincosf(0.5f * p[b * 42 + 28 + 1], &sx, &cx);    // Rx3(1): mask 4
            pr_ = __shfl_xor_sync(0xffffffffu, fvr, 4);
            pi_ = __shfl_xor_sync(0xffffffffu, fvi, 4);
            nr_ = cx * fvr + sx * pi_; ni_ = cx * fvi - sx * pr_;
            fvr = nr_; fvi = ni_;
            sincosf(0.5f * p[b * 42 + 28 + 2], &sx, &cx);    // Rx3(2): mask 2
            pr_ = __shfl_xor_sync(0xffffffffu, fvr, 2);
            pi_ = __shfl_xor_sync(0xffffffffu, fvi, 2);
            nr_ = cx * fvr + sx * pi_; ni_ = cx * fvi - sx * pr_;
            fvr = nr_; fvi = ni_;
            if (tid < 16) { Whr[tid] = fvr; Whi[tid] = fvi; }
        }
        if (tid >= 32 && tid < 32 + NQ) {
            int w = tid - 32;
            float c, s; sincosf(0.5f * cp[b * NQ + w], &s, &c);
            txv[w] = __fdividef(s, c); cxc[w] = c;
        }
        if (tid >= 64 && tid < 64 + NQ) {
            int w = tid - 64;
            float c, s; sincosf(0.5f * p[b * 3 * NQ + 2 * NQ + w], &s, &c);
            t3[w] = __fdividef(s, c); c3c[w] = c;
        }
        if (tid >= 96 && tid < 96 + NQ) {
            int w = tid - 96;
            float c, s; sincosf(0.5f * p[b * 3 * NQ + NQ + w], &s, &c);
            tz[w] = __fdividef(s, c); czc[w] = c;
        }
        if (tid >= 128 && tid < 128 + NQ) {
            int w = tid - 128;
            sincosf(0.5f * p[b * 3 * NQ + w], &s1[w], &c1[w]);
        }
        __syncthreads();

        // kappas (read post-barrier; consumed only after later barriers)
        if (tid == 32)
            kapA[0] = cxc[2] * cxc[3] * czc[4] * czc[5] * czc[6] * czc[7] *
                      cxc[9] * c3c[5] * c3c[6];
        else if (tid == 64)
            kapA[1] = cxc[4] * cxc[5] * czc[8] * czc[9] * czc[10] * czc[11] *
                      cxc[11] * c3c[9] * c3c[10] *
                      cxc[10] * c3c[7] * c3c[8];
        else if (tid == 96)
            kapA[2] = cxc[12] * cxc[13] * c3c[0] * c3c[11] * c3c[12] * c3c[13] *
                      cxc[8] * c3c[3] * c3c[4];

        u64 Ar[16], Ai[16];

        // ====== INIT + P2 (registers).  j = tid[8:5]<<10 | t<<6 | pk<<5 | tid[4:0]
        // reg t <-> wires 4-7, pack = wire 8; warp bits = wires 0-3; lanes = 9-13
        {
            float Pl = 1.0f;
#pragma unroll
            for (int bb = 2; bb <= 4; bb++)       // j bits 4..2 <-> wires 9..11
                Pl *= ((tid >> bb) & 1) ? s1[13 - bb] : c1[13 - bb];
            int pcl = __popc(tid & 0x1C);
            float Cr = chi_r[tid & 3], Ci = chi_i[tid & 3];
            float Wr0 = Whr[tid >> 5], Wi0 = Whi[tid >> 5];
            float Br = Wr0 * Cr - Wi0 * Ci;
            float Bi = Wr0 * Ci + Wi0 * Cr;
            float tr, ti; rot_mi(pcl, Br, Bi, tr, ti);
            Br = tr * Pl; Bi = ti * Pl;
            float c8 = c1[8], s8 = s1[8];
#pragma unroll
            for (int t = 0; t < 16; t++) {
                float f = 1.0f;
#pragma unroll
                for (int k = 0; k < 4; k++)       // t bit k = j bit 6+k = wire 7-k
                    f *= ((t >> k) & 1) ? s1[7 - k] : c1[7 - k];
                float xr, xi; rot_mi(__popc(t), Br, Bi, xr, xi);
                Ar[t] = pk2(xr * f * c8,  xi * f * s8);
                Ai[t] = pk2(xi * f * c8, -xr * f * s8);
            }
        }
        { Gf g = mkgf(txv[2]); xxf<8, 4>(Ar, Ai, g); }   // XXa(4,5)
        { Gf g = mkgf(txv[3]); xxf<2, 1>(Ar, Ai, g); }   // XXa(6,7)
        { Gf g = mkgf(tz[4]);  rzf<8>(Ar, Ai, g); }
        { Gf g = mkgf(tz[5]);  rzf<4>(Ar, Ai, g); }
        { Gf g = mkgf(tz[6]);  rzf<2>(Ar, Ai, g); }
        { Gf g = mkgf(tz[7]);  rzf<1>(Ar, Ai, g); }
        { Gf g = mkgf(txv[9]); xxf<4, 2>(Ar, Ai, g); }   // XXb(5,6)
        { Gf g = mkgf(t3[5]);  rxf<4>(Ar, Ai, g); }
        { Gf g = mkgf(t3[6]);  rxf<2>(Ar, Ai, g); }
        {
            int a = (tid >> 5) * 1060 + (tid & 31);
#pragma unroll
            for (int t = 0; t < 16; t++) {
                int o = a + t * 66; float lo, hi;
                up2(Ar[t], lo, hi); RE[o] = lo; RE[o + 33] = hi;
                up2(Ai[t], lo, hi); IM[o] = lo; IM[o + 33] = hi;
            }
        }
        __syncthreads();

        // ====== P3: reg = wires 8-11, pack = wire 7 (j6); + absorbed XXb(7,8)
        {
            int a = (tid >> 5) * 1060 + ((tid >> 2) & 7) * 132 + (tid & 3);
#pragma unroll
            for (int t = 0; t < 16; t++) {
                int o = a + t * 4 + (t >> 3);
                Ar[t] = pk2(RE[o], RE[o + 66]);
                Ai[t] = pk2(IM[o], IM[o + 66]);
            }
            { Gf g = mkgf(txv[4]);  xxf<8, 4>(Ar, Ai, g); }  // XXa(8,9)
            { Gf g = mkgf(txv[5]);  xxf<2, 1>(Ar, Ai, g); }  // XXa(10,11)
            { Gf g = mkgf(tz[8]);   rzf<8>(Ar, Ai, g); }
            { Gf g = mkgf(tz[9]);   rzf<4>(Ar, Ai, g); }
            { Gf g = mkgf(tz[10]);  rzf<2>(Ar, Ai, g); }
            { Gf g = mkgf(tz[11]);  rzf<1>(Ar, Ai, g); }
            { Gf g = mkgf(txv[11]); xxf<4, 2>(Ar, Ai, g); }  // XXb(9,10)
            {   // XXb(7,8): pack(wire7) x reg bit3(wire8)
                float tv = txv[10]; u64 T = pk2(tv, tv), Tn = pk2(-tv, -tv);
#pragma unroll
                for (int q = 0; q < 8; q++) {
                    u64 xr = Ar[q], xi = Ai[q], yr = Ar[q | 8], yi = Ai[q | 8];
                    Ar[q]     = fma2(T,  swp(yi), xr);
                    Ai[q]     = fma2(Tn, swp(yr), xi);
                    Ar[q | 8] = fma2(T,  swp(xi), yr);
                    Ai[q | 8] = fma2(Tn, swp(xr), yi);
                }
            }
            { Gf g = mkgf(t3[8]); rxf<8>(Ar, Ai, g); }       // Rx3(8)
            {   // Rx3(7): pack gate
                float tv = t3[7]; u64 T = pk2(tv, tv), Tn = pk2(-tv, -tv);
#pragma unroll
                for (int q = 0; q < 16; q++) {
                    u64 r = Ar[q], i = Ai[q];
                    Ar[q] = fma2(T,  swp(i), r);
                    Ai[q] = fma2(Tn, swp(r), i);
                }
            }
            { Gf g = mkgf(t3[9]);   rxf<4>(Ar, Ai, g); }
            { Gf g = mkgf(t3[10]);  rxf<2>(Ar, Ai, g); }
            scale32(Ar, Ai, kapA[0] * kapA[1]);
#pragma unroll
            for (int t = 0; t < 16; t++) {
                int o = a + t * 4 + (t >> 3); float lo, hi;
                up2(Ar[t], lo, hi); RE[o] = lo; RE[o + 66] = hi;
                up2(Ai[t], lo, hi); IM[o] = lo; IM[o + 66] = hi;
            }
        }
        __syncthreads();

        // ====== P5: reg = wires {0,11,12,13} (t3,t2,t1,t0), pack = wire1 (j12)
        //        lanes: tid4=wire3(j10), tid3=wire4(j9), tid2=wire5(j8),
        //               tid1=wire7(j6), tid0=wire8(j5)
        //        warps: tid8=wire2(j11), tid7=wire6(j7), tid6=wire9(j4), tid5=wire10(j3)
        {
            int a5 = ((tid >> 8) & 1) * 2120 + ((tid >> 4) & 1) * 1060
                   + ((tid >> 3) & 1) * 528  + ((tid >> 2) & 1) * 264
                   + ((tid >> 7) & 1) * 132  + ((tid >> 1) & 1) * 66
                   + (tid & 1) * 33 + ((tid >> 6) & 1) * 16 + ((tid >> 5) & 1) * 8;
#pragma unroll
            for (int t = 0; t < 16; t++) {
                int o = a5 + ((t >> 3) & 1) * 8480 + (t & 7);
                Ar[t] = pk2(RE[o], RE[o + 4240]);
                Ai[t] = pk2(IM[o], IM[o + 4240]);
            }
            lgate(Ar, Ai, txv[8], 24);                       // XXb(3,4) lanes 4^3
            lgate(Ar, Ai, t3[3], 16);                        // Rx3(3)
            lgate(Ar, Ai, t3[4], 8);                         // Rx3(4)
            { Gf g = mkgf(txv[12]); xxf<4, 2>(Ar, Ai, g); }  // XXb(11,12)
            { Gf g = mkgf(txv[13]); xxf<1, 8>(Ar, Ai, g); }  // XXb(13,0)
            { Gf g = mkgf(t3[0]);   rxf<8>(Ar, Ai, g); }
            { Gf g = mkgf(t3[11]);  rxf<4>(Ar, Ai, g); }
            { Gf g = mkgf(t3[12]);  rxf<2>(Ar, Ai, g); }
            { Gf g = mkgf(t3[13]);  rxf<1>(Ar, Ai, g); }

            // scaled probabilities -> smem (true prob = kap2^2 * value)
#pragma unroll
            for (int t = 0; t < 16; t++) {
                int o = a5 + ((t >> 3) & 1) * 8480 + (t & 7);
                u64 Pr = fma2(Ai[t], Ai[t], mul2(Ar[t], Ar[t]));
                float lo, hi; up2(Pr, lo, hi);
                RE[o] = lo; RE[o + 4240] = hi;
            }
        }
        __syncthreads();

        // ====== epilogue: inverse-permuted gather + Walsh trees ==============
        float l1[16], a4 = 0.0f;
#pragma unroll
        for (int k = 0; k < 16; k++) {
            int y0 = (k << 10) | tid;
            int y1 = y0 | 512;
            int x0 = d_permtab[y0];
            int x1 = d_permtab[y1];
            float v0 = RE[x0 + (x0 >> 5) + ((x0 >> 10) << 2)];
            float v1 = RE[x1 + (x1 >> 5) + ((x1 >> 10) << 2)];
            l1[k] = v0 + v1;
            a4 += v0 - v1;
        }
        float l2[8], a3 = 0.0f;
#pragma unroll
        for (int k = 0; k < 8; k++) { l2[k] = l1[2*k] + l1[2*k+1]; a3 += l1[2*k] - l1[2*k+1]; }
        float l3[4], a2 = 0.0f;
#pragma unroll
        for (int k = 0; k < 4; k++) { l3[k] = l2[2*k] + l2[2*k+1]; a2 += l2[2*k] - l2[2*k+1]; }
        float l4[2], a1 = 0.0f;
#pragma unroll
        for (int k = 0; k < 2; k++) { l4[k] = l3[2*k] + l3[2*k+1]; a1 += l3[2*k] - l3[2*k+1]; }
        float T  = l4[0] + l4[1];
        float a0 = l4[0] - l4[1];

        float av[5] = {a0, a1, a2, a3, a4};
        float d[5];
#pragma unroll
        for (int k = 0; k < 5; k++) {
            float pT = __shfl_xor_sync(0xffffffffu, T, 1 << k);
            d[k] = T - pT;
            T += pT;
#pragma unroll
            for (int j = 0; j < 5; j++)
                av[j] += __shfl_xor_sync(0xffffffffu, av[j], 1 << k);
#pragma unroll
            for (int m = 0; m < 5; m++)
                if (m < k) d[m] += __shfl_xor_sync(0xffffffffu, d[m], 1 << k);
        }
        if ((tid & 31) == 0) {
            int wp = tid >> 5;
#pragma unroll
            for (int j = 0; j < 5; j++) red[wp][j] = av[j];
#pragma unroll
            for (int k = 0; k < 5; k++) red[wp][5 + k] = d[k];
            red[wp][10] = T;
        }
        __syncthreads();

        if (tid < NQ * 32) {
            int w = tid >> 5;
            int r = tid & 31;
            float v = 0.0f;
            if (r < 16) {
                if (w < 5) {
                    v = red[r][w];                        // wires 0-4
                } else if (w < 9) {
                    float Tt = red[r][10];                // wires 5-8
                    v = ((r >> (8 - w)) & 1) ? -Tt : Tt;
                } else {
                    v = red[r][5 + (13 - w)];             // wires 9-13
                }
            }
#pragma unroll
            for (int o = 8; o; o >>= 1) v += __shfl_xor_sync(0xffffffffu, v, o);
            if (r == 0) {
                float k5 = kapA[2];
                out[b * NQ + w] = (v * k5) * k5;
            }
        }
    }
}

extern "C" void kernel_launch(void* const* d_in, const int* in_sizes, int n_in,
                              void* d_out, int out_size) {
    const float* cp = (const float*)d_in[0];   // (512, 14)
    const float* p  = (const float*)d_in[1];   // (512, 3, 14)
    float* out      = (float*)d_out;           // (512, 14)

    build_perm_kernel<<<NS / 1024, 1024>>>();

    size_t smem = (size_t)PAD_SLOTS * 2 * sizeof(float);  // 135680 bytes
    cudaFuncSetAttribute(quantum_kernel,
                         cudaFuncAttributeMaxDynamicSharedMemorySize, (int)smem);
    quantum_kernel<<<GRID, NTH, smem>>>(cp, p, out);
}